// round 9
// baseline (speedup 1.0000x reference)
#include <cuda_runtime.h>
#include <cuda_fp16.h>
#include <cstdint>

#define NV 50000
#define NE 400000
#define HVD 128
#define NOUT 256
#define NT 391
#define NROWS_PAD (NT * 128)
#define GRID_GEMM 148

// ---------------------------------------------------------------------------
// Device scratch
// ---------------------------------------------------------------------------
__device__ __half g_Y[(size_t)NV * HVD];              // fp16: hv@(Wl_a+Wl_b)+bl
__device__ int    g_flag[NV];
__device__ __align__(16) __half g_Ah[(size_t)NROWS_PAD * HVD];
__device__ __align__(16) __half g_Bhi[HVD * NOUT];
__device__ __align__(16) __half g_Blo[HVD * NOUT];

#define A_STRIDE 272
#define B_STRIDE 528
#define S_A0   0
#define S_A1   34816
#define S_BHI  69632
#define S_BLO  137216
#define S_TOTAL 204800

__device__ __forceinline__ uint32_t smem_u32(const void* p) {
    uint32_t a;
    asm("{ .reg .u64 t; cvta.to.shared.u64 t, %1; cvt.u32.u64 %0, t; }"
        : "=r"(a) : "l"(p));
    return a;
}
#define LDMX4(r0, r1, r2, r3, a)                                              \
    asm volatile("ldmatrix.sync.aligned.m8n8.x4.shared.b16 {%0,%1,%2,%3}, [%4];" \
                 : "=r"(r0), "=r"(r1), "=r"(r2), "=r"(r3) : "r"(a))
#define LDMX4T(r0, r1, r2, r3, a)                                             \
    asm volatile("ldmatrix.sync.aligned.m8n8.x4.trans.shared.b16 {%0,%1,%2,%3}, [%4];" \
                 : "=r"(r0), "=r"(r1), "=r"(r2), "=r"(r3) : "r"(a))
#define MMA16816(d, a0, a1, a2, a3, b0, b1)                                   \
    asm volatile("mma.sync.aligned.m16n8k16.row.col.f32.f16.f16.f32 "         \
                 "{%0,%1,%2,%3}, {%4,%5,%6,%7}, {%8,%9}, {%0,%1,%2,%3};"      \
                 : "+f"((d)[0]), "+f"((d)[1]), "+f"((d)[2]), "+f"((d)[3])     \
                 : "r"(a0), "r"(a1), "r"(a2), "r"(a3), "r"(b0), "r"(b1))
#define CP_ASYNC16(dst, src)                                                  \
    asm volatile("cp.async.cg.shared.global [%0], [%1], 16;"                  \
                 :: "r"(dst), "l"(src) : "memory")
#define CP_COMMIT()   asm volatile("cp.async.commit_group;" ::: "memory")
#define CP_WAIT(n)    asm volatile("cp.async.wait_group %0;" :: "n"(n) : "memory")

// ---------------------------------------------------------------------------
// Kernel 1: zero flags + build split-fp16 B images.
// ---------------------------------------------------------------------------
__global__ void prep_kernel(const float* __restrict__ Wa,
                            const float* __restrict__ Wl) {
    int idx = blockIdx.x * blockDim.x + threadIdx.x;
    int stride = gridDim.x * blockDim.x;
    for (int i = idx; i < NV; i += stride) g_flag[i] = 0;
    for (int i = idx; i < HVD * NOUT; i += stride) {
        int k = i >> 8;
        int n = i & 255;
        float v;
        if (n < HVD) v = Wa[k * HVD + n];
        else {
            int c = n - HVD;
            v = Wl[k * 128 + c] + Wl[(134 + k) * 128 + c];
        }
        __half hi = __float2half_rn(v);
        __half lo = __float2half_rn(v - __half2float(hi));
        g_Bhi[i] = hi;
        g_Blo[i] = lo;
    }
}

// ---------------------------------------------------------------------------
// Kernel 2: convert hv -> fp16 g_Ah (zero-padded) AND mark edge flags.
// ---------------------------------------------------------------------------
__global__ void convert_flag_kernel(const float* __restrict__ hv,
                                    const int* __restrict__ eu,
                                    const int* __restrict__ ev) {
    int idx = blockIdx.x * blockDim.x + threadIdx.x;
    if (idx < NE) {
        g_flag[__ldg(eu + idx)] = 1;
        g_flag[__ldg(ev + idx)] = 1;
    }
    const int total = NROWS_PAD * HVD / 8;
    if (idx >= total) return;
    int row = idx >> 4;
    uint4 out = make_uint4(0, 0, 0, 0);
    if (row < NV) {
        const float4* src = reinterpret_cast<const float4*>(hv) + idx * 2;
        float4 v0 = src[0];
        float4 v1 = src[1];
        __half2 h0 = __floats2half2_rn(v0.x, v0.y);
        __half2 h1 = __floats2half2_rn(v0.z, v0.w);
        __half2 h2 = __floats2half2_rn(v1.x, v1.y);
        __half2 h3 = __floats2half2_rn(v1.z, v1.w);
        out.x = *reinterpret_cast<uint32_t*>(&h0);
        out.y = *reinterpret_cast<uint32_t*>(&h1);
        out.z = *reinterpret_cast<uint32_t*>(&h2);
        out.w = *reinterpret_cast<uint32_t*>(&h3);
    }
    *(reinterpret_cast<uint4*>(g_Ah) + idx) = out;
}

// ---------------------------------------------------------------------------
// A-tile prefetch: 2048 16B chunks, 512 threads x 4 iters.
// ---------------------------------------------------------------------------
__device__ __forceinline__ void issue_a_tile(uint32_t dst_base, int tile, int tid) {
    const char* src = reinterpret_cast<const char*>(g_Ah)
                    + (size_t)tile * 128 * HVD * 2;
    #pragma unroll
    for (int it = 0; it < 4; it++) {
        int idx = tid + it * 512;
        int row = idx >> 4;
        int c = idx & 15;
        CP_ASYNC16(dst_base + (uint32_t)row * A_STRIDE + (uint32_t)c * 16,
                   src + (size_t)row * 256 + (size_t)c * 16);
    }
}

// ---------------------------------------------------------------------------
// Kernel 3: persistent split-fp16 HMMA GEMM, 512 threads, SW-pipelined frags.
//   2 phases of 128 cols; per-phase warp grid 4(m) x 4(n), warp tile 32x32.
//   Fragment double-buffer: load k+1 fragments while k's mma execute.
// ---------------------------------------------------------------------------
__global__ void __launch_bounds__(512, 1)
gemm_kernel(const float* __restrict__ ba,
            const float* __restrict__ bl,
            float* __restrict__ out_mv) {
    extern __shared__ __align__(16) unsigned char smem[];
    const uint32_t sb = smem_u32(smem);
    const int tid = threadIdx.x;
    const int wid = tid >> 5;
    const int lane = tid & 31;
    const int warp_m = wid & 3;
    const int warp_n = wid >> 2;      // 0..3 within a 128-col phase

    // ---- B images -> SMEM once ----
    {
        const char* sh = reinterpret_cast<const char*>(g_Bhi);
        const char* sl = reinterpret_cast<const char*>(g_Blo);
        #pragma unroll
        for (int it = 0; it < 8; it++) {
            int idx = tid + it * 512;      // 0..4095
            int k = idx >> 5;
            int c = idx & 31;
            uint32_t off = (uint32_t)k * B_STRIDE + (uint32_t)c * 16;
            CP_ASYNC16(sb + S_BHI + off, sh + idx * 16);
            CP_ASYNC16(sb + S_BLO + off, sl + idx * 16);
        }
        CP_COMMIT();
    }

    int tile = blockIdx.x;
    issue_a_tile(sb + S_A0, tile, tid);
    CP_COMMIT();

    const uint32_t a_lane_off = (uint32_t)(warp_m * 32 + (lane & 15)) * A_STRIDE
                              + (uint32_t)(lane >> 4) * 16;
    const uint32_t b_lane_off = (uint32_t)(lane & 15) * B_STRIDE
                              + (uint32_t)(warp_n * 32 + (lane >> 4) * 8) * 2;

// load fragments for k-step K into buffer slot S
#define LOAD_FRAGS(K, S)                                                      \
    do {                                                                      \
        LDMX4(af[S][0], af[S][1], af[S][2], af[S][3],                         \
              aHi + (uint32_t)(K) * 32);                                      \
        LDMX4(af[S][4], af[S][5], af[S][6], af[S][7],                         \
              aHi + (uint32_t)(K) * 32 + (16 * A_STRIDE));                    \
        LDMX4T(bh[S][0], bh[S][1], bh[S][2], bh[S][3],                        \
               bHi + (uint32_t)(K) * (16 * B_STRIDE));                        \
        LDMX4T(bh[S][4], bh[S][5], bh[S][6], bh[S][7],                        \
               bHi + (uint32_t)(K) * (16 * B_STRIDE) + 32);                   \
        LDMX4T(bo[S][0], bo[S][1], bo[S][2], bo[S][3],                        \
               bLo + (uint32_t)(K) * (16 * B_STRIDE));                        \
        LDMX4T(bo[S][4], bo[S][5], bo[S][6], bo[S][7],                        \
               bLo + (uint32_t)(K) * (16 * B_STRIDE) + 32);                   \
    } while (0)

#define MMA_SET(S)                                                            \
    do {                                                                      \
        _Pragma("unroll")                                                     \
        for (int mi = 0; mi < 2; mi++) {                                      \
            _Pragma("unroll")                                                 \
            for (int ni = 0; ni < 4; ni++)                                    \
                MMA16816(acc[mi * 4 + ni],                                    \
                         af[S][mi*4+0], af[S][mi*4+1], af[S][mi*4+2], af[S][mi*4+3], \
                         bh[S][(ni >> 1) * 4 + (ni & 1) * 2],                 \
                         bh[S][(ni >> 1) * 4 + (ni & 1) * 2 + 1]);            \
            _Pragma("unroll")                                                 \
            for (int ni = 0; ni < 4; ni++)                                    \
                MMA16816(acc[mi * 4 + ni],                                    \
                         af[S][mi*4+0], af[S][mi*4+1], af[S][mi*4+2], af[S][mi*4+3], \
                         bo[S][(ni >> 1) * 4 + (ni & 1) * 2],                 \
                         bo[S][(ni >> 1) * 4 + (ni & 1) * 2 + 1]);            \
        }                                                                     \
    } while (0)

    int buf = 0;
    while (tile < NT) {
        int next = tile + GRID_GEMM;
        if (next < NT) {
            issue_a_tile(sb + (buf ? S_A0 : S_A1), next, tid);
            CP_COMMIT();
            CP_WAIT(1);
        } else {
            CP_WAIT(0);
        }
        __syncthreads();

        const uint32_t aHi = sb + (buf ? S_A1 : S_A0) + a_lane_off;
        const int row0 = tile * 128;
        const int r_base = row0 + warp_m * 32 + (lane >> 2);
        const int cbase = warp_n * 32;

        #pragma unroll
        for (int phase = 0; phase < 2; phase++) {
            const uint32_t bHi = sb + S_BHI + b_lane_off + (uint32_t)phase * 256;
            const uint32_t bLo = sb + S_BLO + b_lane_off + (uint32_t)phase * 256;

            float acc[8][4];
            #pragma unroll
            for (int t = 0; t < 8; t++)
                #pragma unroll
                for (int j = 0; j < 4; j++) acc[t][j] = 0.f;

            uint32_t af[2][8], bh[2][8], bo[2][8];
            LOAD_FRAGS(0, 0);
            #pragma unroll
            for (int k = 0; k < 8; k++) {
                const int cur = k & 1;
                const int nxt = cur ^ 1;
                if (k < 7) {
                    if (nxt) LOAD_FRAGS(k + 1, 1);
                    else     LOAD_FRAGS(k + 1, 0);
                }
                if (cur) MMA_SET(1);
                else     MMA_SET(0);
            }

            // ---- epilogue ----
            if (phase == 0) {
                #pragma unroll
                for (int mi = 0; mi < 2; mi++) {
                    int r0r = r_base + mi * 16;
                    int fl0 = (r0r     < NV) ? g_flag[r0r]     : 0;
                    int fl1 = (r0r + 8 < NV) ? g_flag[r0r + 8] : 0;
                    #pragma unroll
                    for (int ni = 0; ni < 4; ni++) {
                        int c = cbase + ni * 8 + (lane & 3) * 2;
                        float* ac = acc[mi * 4 + ni];
                        float b0 = __ldg(ba + c), b1 = __ldg(ba + c + 1);
                        #pragma unroll
                        for (int h = 0; h < 2; h++) {
                            int r = r0r + h * 8;
                            if (r >= NV) continue;
                            int fl = h ? fl1 : fl0;
                            float x0 = ac[h * 2 + 0] + b0;
                            float x1 = ac[h * 2 + 1] + b1;
                            float l0 = x0 > 0.f ? x0 : 0.01f * x0;
                            float l1 = x1 > 0.f ? x1 : 0.01f * x1;
                            float e0 = l0 > 0.f ? l0 : expm1f(l0);
                            float e1 = l1 > 0.f ? l1 : expm1f(l1);
                            e0 = fl ? e0 : 0.f;
                            e1 = fl ? e1 : 0.f;
                            asm volatile("st.global.cs.v2.f32 [%0], {%1,%2};"
                                         :: "l"(out_mv + (size_t)r * HVD + c),
                                            "f"(e0), "f"(e1) : "memory");
                        }
                    }
                }
            } else {
                #pragma unroll
                for (int mi = 0; mi < 2; mi++) {
                    int r0r = r_base + mi * 16;
                    #pragma unroll
                    for (int ni = 0; ni < 4; ni++) {
                        int cy = cbase + ni * 8 + (lane & 3) * 2;
                        float* ac = acc[mi * 4 + ni];
                        float b0 = __ldg(bl + cy), b1 = __ldg(bl + cy + 1);
                        #pragma unroll
                        for (int h = 0; h < 2; h++) {
                            int r = r0r + h * 8;
                            if (r >= NV) continue;
                            __half2 o = __floats2half2_rn(ac[h * 2 + 0] + b0,
                                                          ac[h * 2 + 1] + b1);
                            *reinterpret_cast<__half2*>(g_Y + (size_t)r * HVD + cy) = o;
                        }
                    }
                }
            }
        }
        __syncthreads();
        buf ^= 1;
        tile = next;
    }
#undef LOAD_FRAGS
#undef MMA_SET
}

// ---------------------------------------------------------------------------
// Kernel 4: per-edge output, 4 edges per warp, fp16 Y gathers.
// ---------------------------------------------------------------------------
__global__ __launch_bounds__(256)
void edge_kernel(const int* __restrict__ eu, const int* __restrict__ ev,
                 float* __restrict__ out_me) {
    int warp = (blockIdx.x * blockDim.x + threadIdx.x) >> 5;
    int lane = threadIdx.x & 31;
    int e0 = warp * 4;
    if (e0 >= NE) return;
    const int4 us = *reinterpret_cast<const int4*>(eu + e0);
    const int4 vs = *reinterpret_cast<const int4*>(ev + e0);
    const uint2* Y = reinterpret_cast<const uint2*>(g_Y);

    uint2 a0 = __ldg(Y + (size_t)us.x * 32 + lane);
    uint2 b0 = __ldg(Y + (size_t)vs.x * 32 + lane);
    uint2 a1 = __ldg(Y + (size_t)us.y * 32 + lane);
    uint2 b1 = __ldg(Y + (size_t)vs.y * 32 + lane);
    uint2 a2 = __ldg(Y + (size_t)us.z * 32 + lane);
    uint2 b2 = __ldg(Y + (size_t)vs.z * 32 + lane);
    uint2 a3 = __ldg(Y + (size_t)us.w * 32 + lane);
    uint2 b3 = __ldg(Y + (size_t)vs.w * 32 + lane);

    float* p = out_me + (size_t)e0 * HVD + lane * 4;
#define EDGE_OUT(av, bv, idx) do {                                            \
        float2 alo = __half22float2(*reinterpret_cast<__half2*>(&av.x));      \
        float2 ahi = __half22float2(*reinterpret_cast<__half2*>(&av.y));      \
        float2 blo = __half22float2(*reinterpret_cast<__half2*>(&bv.x));      \
        float2 bhi = __half22float2(*reinterpret_cast<__half2*>(&bv.y));      \
        float4 o;                                                             \
        o.x = alo.x + blo.x; o.y = alo.y + blo.y;                             \
        o.z = ahi.x + bhi.x; o.w = ahi.y + bhi.y;                             \
        o.x = o.x > 0.f ? o.x : 0.01f * o.x;                                  \
        o.y = o.y > 0.f ? o.y : 0.01f * o.y;                                  \
        o.z = o.z > 0.f ? o.z : 0.01f * o.z;                                  \
        o.w = o.w > 0.f ? o.w : 0.01f * o.w;                                  \
        asm volatile("st.global.cs.v4.f32 [%0], {%1,%2,%3,%4};"               \
                     :: "l"(p + (idx) * HVD), "f"(o.x), "f"(o.y),             \
                        "f"(o.z), "f"(o.w) : "memory");                       \
    } while (0)
    EDGE_OUT(a0, b0, 0);
    EDGE_OUT(a1, b1, 1);
    EDGE_OUT(a2, b2, 2);
    EDGE_OUT(a3, b3, 3);
#undef EDGE_OUT
}

// ---------------------------------------------------------------------------
// Launch.
// ---------------------------------------------------------------------------
extern "C" void kernel_launch(void* const* d_in, const int* in_sizes, int n_in,
                              void* d_out, int out_size) {
    const float* hv = (const float*)d_in[0];
    const int*   eu = (const int*)d_in[4];
    const int*   ev = (const int*)d_in[5];
    const float* Wa = (const float*)d_in[6];
    const float* ba = (const float*)d_in[7];
    const float* Wl = (const float*)d_in[10];
    const float* bl = (const float*)d_in[11];
    float* out = (float*)d_out;

    static bool attr_set = false;
    if (!attr_set) {
        cudaFuncSetAttribute(gemm_kernel,
                             cudaFuncAttributeMaxDynamicSharedMemorySize, S_TOTAL);
        attr_set = true;
    }

    prep_kernel<<<128, 256>>>(Wa, Wl);
    convert_flag_kernel<<<(NROWS_PAD * HVD / 8 + 255) / 256, 256>>>(hv, eu, ev);
    gemm_kernel<<<GRID_GEMM, 512, S_TOTAL>>>(ba, bl, out);
    edge_kernel<<<(NE / 4 * 32 + 255) / 256, 256>>>(eu, ev,
                                                    out + (size_t)NV * HVD);
}

// round 10
// speedup vs baseline: 1.2527x; 1.2527x over previous
#include <cuda_runtime.h>
#include <cuda_fp16.h>
#include <cstdint>

#define NV 50000
#define NE 400000
#define HVD 128
#define NOUT 256
#define NT 391
#define NROWS_PAD (NT * 128)
#define GRID_GEMM 148

// ---------------------------------------------------------------------------
// Device scratch
// ---------------------------------------------------------------------------
__device__ __half g_Y[(size_t)NV * HVD];              // fp16: hv@(Wl_a+Wl_b)+bl
__device__ int    g_flag[NV];
__device__ __align__(16) __half g_Ah[(size_t)NROWS_PAD * HVD];
__device__ __align__(16) __half g_Bh[HVD * NOUT];     // [k][n] fp16 (hi only)

#define A_STRIDE 272
#define B_STRIDE 528
#define S_A0   0
#define S_A1   34816
#define S_B    69632
#define S_TOTAL 137216

__device__ __forceinline__ uint32_t smem_u32(const void* p) {
    uint32_t a;
    asm("{ .reg .u64 t; cvta.to.shared.u64 t, %1; cvt.u32.u64 %0, t; }"
        : "=r"(a) : "l"(p));
    return a;
}
#define LDMX4(r0, r1, r2, r3, a)                                              \
    asm volatile("ldmatrix.sync.aligned.m8n8.x4.shared.b16 {%0,%1,%2,%3}, [%4];" \
                 : "=r"(r0), "=r"(r1), "=r"(r2), "=r"(r3) : "r"(a))
#define LDMX4T(r0, r1, r2, r3, a)                                             \
    asm volatile("ldmatrix.sync.aligned.m8n8.x4.trans.shared.b16 {%0,%1,%2,%3}, [%4];" \
                 : "=r"(r0), "=r"(r1), "=r"(r2), "=r"(r3) : "r"(a))
#define MMA16816(d, a0, a1, a2, a3, b0, b1)                                   \
    asm volatile("mma.sync.aligned.m16n8k16.row.col.f32.f16.f16.f32 "         \
                 "{%0,%1,%2,%3}, {%4,%5,%6,%7}, {%8,%9}, {%0,%1,%2,%3};"      \
                 : "+f"((d)[0]), "+f"((d)[1]), "+f"((d)[2]), "+f"((d)[3])     \
                 : "r"(a0), "r"(a1), "r"(a2), "r"(a3), "r"(b0), "r"(b1))
#define CP_ASYNC16(dst, src)                                                  \
    asm volatile("cp.async.cg.shared.global [%0], [%1], 16;"                  \
                 :: "r"(dst), "l"(src) : "memory")
#define CP_COMMIT()   asm volatile("cp.async.commit_group;" ::: "memory")
#define CP_WAIT(n)    asm volatile("cp.async.wait_group %0;" :: "n"(n) : "memory")

// ---------------------------------------------------------------------------
// Kernel 1: zero flags + build fp16 B image.
// ---------------------------------------------------------------------------
__global__ void prep_kernel(const float* __restrict__ Wa,
                            const float* __restrict__ Wl) {
    int idx = blockIdx.x * blockDim.x + threadIdx.x;
    int stride = gridDim.x * blockDim.x;
    for (int i = idx; i < NV; i += stride) g_flag[i] = 0;
    for (int i = idx; i < HVD * NOUT; i += stride) {
        int k = i >> 8;
        int n = i & 255;
        float v;
        if (n < HVD) v = Wa[k * HVD + n];
        else {
            int c = n - HVD;
            v = Wl[k * 128 + c] + Wl[(134 + k) * 128 + c];
        }
        g_Bh[i] = __float2half_rn(v);
    }
}

// ---------------------------------------------------------------------------
// Kernel 2: convert hv -> fp16 g_Ah (zero-padded) AND mark edge flags.
// ---------------------------------------------------------------------------
__global__ void convert_flag_kernel(const float* __restrict__ hv,
                                    const int* __restrict__ eu,
                                    const int* __restrict__ ev) {
    int idx = blockIdx.x * blockDim.x + threadIdx.x;
    if (idx < NE) {
        g_flag[__ldg(eu + idx)] = 1;
        g_flag[__ldg(ev + idx)] = 1;
    }
    const int total = NROWS_PAD * HVD / 8;
    if (idx >= total) return;
    int row = idx >> 4;
    uint4 out = make_uint4(0, 0, 0, 0);
    if (row < NV) {
        const float4* src = reinterpret_cast<const float4*>(hv) + idx * 2;
        float4 v0 = src[0];
        float4 v1 = src[1];
        __half2 h0 = __floats2half2_rn(v0.x, v0.y);
        __half2 h1 = __floats2half2_rn(v0.z, v0.w);
        __half2 h2 = __floats2half2_rn(v1.x, v1.y);
        __half2 h3 = __floats2half2_rn(v1.z, v1.w);
        out.x = *reinterpret_cast<uint32_t*>(&h0);
        out.y = *reinterpret_cast<uint32_t*>(&h1);
        out.z = *reinterpret_cast<uint32_t*>(&h2);
        out.w = *reinterpret_cast<uint32_t*>(&h3);
    }
    *(reinterpret_cast<uint4*>(g_Ah) + idx) = out;
}

// ---------------------------------------------------------------------------
// A-tile prefetch: 2048 16B chunks, 1024 threads x 2 iters.
// ---------------------------------------------------------------------------
__device__ __forceinline__ void issue_a_tile(uint32_t dst_base, int tile, int tid) {
    const char* src = reinterpret_cast<const char*>(g_Ah)
                    + (size_t)tile * 128 * HVD * 2;
    #pragma unroll
    for (int it = 0; it < 2; it++) {
        int idx = tid + it * 1024;
        int row = idx >> 4;
        int c = idx & 15;
        CP_ASYNC16(dst_base + (uint32_t)row * A_STRIDE + (uint32_t)c * 16,
                   src + (size_t)row * 256 + (size_t)c * 16);
    }
}

// ---------------------------------------------------------------------------
// Kernel 3: persistent single-pass fp16 HMMA GEMM, 1024 threads (32 warps).
//   Warp grid 4(m) x 8(n), warp tile 32x32, full 256 cols at once.
//   warp_n 0..3 -> mv cols; warp_n 4..7 -> Y cols (fp16, bl folded).
// ---------------------------------------------------------------------------
__global__ void __launch_bounds__(1024, 1)
gemm_kernel(const float* __restrict__ ba,
            const float* __restrict__ bl,
            float* __restrict__ out_mv) {
    extern __shared__ __align__(16) unsigned char smem[];
    const uint32_t sb = smem_u32(smem);
    const int tid = threadIdx.x;
    const int wid = tid >> 5;
    const int lane = tid & 31;
    const int warp_m = wid & 3;
    const int warp_n = wid >> 2;

    // ---- B image -> SMEM once ----
    {
        const char* sh = reinterpret_cast<const char*>(g_Bh);
        #pragma unroll
        for (int it = 0; it < 4; it++) {
            int idx = tid + it * 1024;     // 0..4095 (32 chunks x 128 rows)
            int k = idx >> 5;
            int c = idx & 31;
            CP_ASYNC16(sb + S_B + (uint32_t)k * B_STRIDE + (uint32_t)c * 16,
                       sh + idx * 16);
        }
        CP_COMMIT();
    }

    int tile = blockIdx.x;
    issue_a_tile(sb + S_A0, tile, tid);
    CP_COMMIT();

    const uint32_t a_lane_off = (uint32_t)(warp_m * 32 + (lane & 15)) * A_STRIDE
                              + (uint32_t)(lane >> 4) * 16;
    const uint32_t bB = sb + S_B + (uint32_t)(lane & 15) * B_STRIDE
                      + (uint32_t)(warp_n * 32 + (lane >> 4) * 8) * 2;

    int buf = 0;
    while (tile < NT) {
        int next = tile + GRID_GEMM;
        if (next < NT) {
            issue_a_tile(sb + (buf ? S_A0 : S_A1), next, tid);
            CP_COMMIT();
            CP_WAIT(1);
        } else {
            CP_WAIT(0);
        }
        __syncthreads();

        const uint32_t aHi = sb + (buf ? S_A1 : S_A0) + a_lane_off;

        float acc[8][4];
        #pragma unroll
        for (int t = 0; t < 8; t++)
            #pragma unroll
            for (int j = 0; j < 4; j++) acc[t][j] = 0.f;

        #pragma unroll
        for (int k = 0; k < 8; k++) {
            uint32_t af[2][4], bf[2][4];
            #pragma unroll
            for (int mi = 0; mi < 2; mi++)
                LDMX4(af[mi][0], af[mi][1], af[mi][2], af[mi][3],
                      aHi + (uint32_t)k * 32 + (uint32_t)mi * (16 * A_STRIDE));
            #pragma unroll
            for (int nb = 0; nb < 2; nb++)
                LDMX4T(bf[nb][0], bf[nb][1], bf[nb][2], bf[nb][3],
                       bB + (uint32_t)k * (16 * B_STRIDE) + (uint32_t)nb * 32);
            #pragma unroll
            for (int mi = 0; mi < 2; mi++)
                #pragma unroll
                for (int ni = 0; ni < 4; ni++)
                    MMA16816(acc[mi * 4 + ni],
                             af[mi][0], af[mi][1], af[mi][2], af[mi][3],
                             bf[ni >> 1][(ni & 1) * 2], bf[ni >> 1][(ni & 1) * 2 + 1]);
        }

        // ---- epilogue ----
        const int row0 = tile * 128;
        const int r_base = row0 + warp_m * 32 + (lane >> 2);
        const int cbase = (warp_n & 3) * 32;
        if (warp_n < 4) {
            // mv path: elu(leaky(x+ba)) masked by flag; exp via fast __expf
            #pragma unroll
            for (int mi = 0; mi < 2; mi++) {
                int r0r = r_base + mi * 16;
                int fl0 = (r0r     < NV) ? g_flag[r0r]     : 0;
                int fl1 = (r0r + 8 < NV) ? g_flag[r0r + 8] : 0;
                #pragma unroll
                for (int ni = 0; ni < 4; ni++) {
                    int c = cbase + ni * 8 + (lane & 3) * 2;
                    float* ac = acc[mi * 4 + ni];
                    float b0 = __ldg(ba + c), b1 = __ldg(ba + c + 1);
                    #pragma unroll
                    for (int h = 0; h < 2; h++) {
                        int r = r0r + h * 8;
                        if (r >= NV) continue;
                        int fl = h ? fl1 : fl0;
                        float x0 = ac[h * 2 + 0] + b0;
                        float x1 = ac[h * 2 + 1] + b1;
                        // leaky (slope .01) then elu; for x<0: elu(0.01x)=exp(0.01x)-1
                        float e0 = x0 > 0.f ? x0 : (__expf(0.01f * x0) - 1.f);
                        float e1 = x1 > 0.f ? x1 : (__expf(0.01f * x1) - 1.f);
                        e0 = fl ? e0 : 0.f;
                        e1 = fl ? e1 : 0.f;
                        asm volatile("st.global.cs.v2.f32 [%0], {%1,%2};"
                                     :: "l"(out_mv + (size_t)r * HVD + c),
                                        "f"(e0), "f"(e1) : "memory");
                    }
                }
            }
        } else {
            // Y path (fp16, bl folded)
            #pragma unroll
            for (int mi = 0; mi < 2; mi++) {
                int r0r = r_base + mi * 16;
                #pragma unroll
                for (int ni = 0; ni < 4; ni++) {
                    int cy = cbase + ni * 8 + (lane & 3) * 2;
                    float* ac = acc[mi * 4 + ni];
                    float b0 = __ldg(bl + cy), b1 = __ldg(bl + cy + 1);
                    #pragma unroll
                    for (int h = 0; h < 2; h++) {
                        int r = r0r + h * 8;
                        if (r >= NV) continue;
                        __half2 o = __floats2half2_rn(ac[h * 2 + 0] + b0,
                                                      ac[h * 2 + 1] + b1);
                        *reinterpret_cast<__half2*>(g_Y + (size_t)r * HVD + cy) = o;
                    }
                }
            }
        }
        __syncthreads();
        buf ^= 1;
        tile = next;
    }
}

// ---------------------------------------------------------------------------
// Kernel 4: per-edge output, 4 edges per warp, fp16 Y gathers.
//   me[e] = leaky_relu(Yb[u] + Yb[v])
// ---------------------------------------------------------------------------
__global__ __launch_bounds__(256)
void edge_kernel(const int* __restrict__ eu, const int* __restrict__ ev,
                 float* __restrict__ out_me) {
    int warp = (blockIdx.x * blockDim.x + threadIdx.x) >> 5;
    int lane = threadIdx.x & 31;
    int e0 = warp * 4;
    if (e0 >= NE) return;
    const int4 us = *reinterpret_cast<const int4*>(eu + e0);
    const int4 vs = *reinterpret_cast<const int4*>(ev + e0);
    const uint2* Y = reinterpret_cast<const uint2*>(g_Y);

    uint2 a0 = __ldg(Y + (size_t)us.x * 32 + lane);
    uint2 b0 = __ldg(Y + (size_t)vs.x * 32 + lane);
    uint2 a1 = __ldg(Y + (size_t)us.y * 32 + lane);
    uint2 b1 = __ldg(Y + (size_t)vs.y * 32 + lane);
    uint2 a2 = __ldg(Y + (size_t)us.z * 32 + lane);
    uint2 b2 = __ldg(Y + (size_t)vs.z * 32 + lane);
    uint2 a3 = __ldg(Y + (size_t)us.w * 32 + lane);
    uint2 b3 = __ldg(Y + (size_t)vs.w * 32 + lane);

    float* p = out_me + (size_t)e0 * HVD + lane * 4;
#define EDGE_OUT(av, bv, idx) do {                                            \
        float2 alo = __half22float2(*reinterpret_cast<__half2*>(&av.x));      \
        float2 ahi = __half22float2(*reinterpret_cast<__half2*>(&av.y));      \
        float2 blo = __half22float2(*reinterpret_cast<__half2*>(&bv.x));      \
        float2 bhi = __half22float2(*reinterpret_cast<__half2*>(&bv.y));      \
        float4 o;                                                             \
        o.x = alo.x + blo.x; o.y = alo.y + blo.y;                             \
        o.z = ahi.x + bhi.x; o.w = ahi.y + bhi.y;                             \
        o.x = o.x > 0.f ? o.x : 0.01f * o.x;                                  \
        o.y = o.y > 0.f ? o.y : 0.01f * o.y;                                  \
        o.z = o.z > 0.f ? o.z : 0.01f * o.z;                                  \
        o.w = o.w > 0.f ? o.w : 0.01f * o.w;                                  \
        asm volatile("st.global.cs.v4.f32 [%0], {%1,%2,%3,%4};"               \
                     :: "l"(p + (idx) * HVD), "f"(o.x), "f"(o.y),             \
                        "f"(o.z), "f"(o.w) : "memory");                       \
    } while (0)
    EDGE_OUT(a0, b0, 0);
    EDGE_OUT(a1, b1, 1);
    EDGE_OUT(a2, b2, 2);
    EDGE_OUT(a3, b3, 3);
#undef EDGE_OUT
}

// ---------------------------------------------------------------------------
// Launch.
// ---------------------------------------------------------------------------
extern "C" void kernel_launch(void* const* d_in, const int* in_sizes, int n_in,
                              void* d_out, int out_size) {
    const float* hv = (const float*)d_in[0];
    const int*   eu = (const int*)d_in[4];
    const int*   ev = (const int*)d_in[5];
    const float* Wa = (const float*)d_in[6];
    const float* ba = (const float*)d_in[7];
    const float* Wl = (const float*)d_in[10];
    const float* bl = (const float*)d_in[11];
    float* out = (float*)d_out;

    static bool attr_set = false;
    if (!attr_set) {
        cudaFuncSetAttribute(gemm_kernel,
                             cudaFuncAttributeMaxDynamicSharedMemorySize, S_TOTAL);
        attr_set = true;
    }

    prep_kernel<<<128, 256>>>(Wa, Wl);
    convert_flag_kernel<<<(NROWS_PAD * HVD / 8 + 255) / 256, 256>>>(hv, eu, ev);
    gemm_kernel<<<GRID_GEMM, 1024, S_TOTAL>>>(ba, bl, out);
    edge_kernel<<<(NE / 4 * 32 + 255) / 256, 256>>>(eu, ev,
                                                    out + (size_t)NV * HVD);
}

// round 11
// speedup vs baseline: 1.2596x; 1.0055x over previous
#include <cuda_runtime.h>
#include <cuda_fp16.h>
#include <cstdint>

#define NV 50000
#define NE 400000
#define HVD 128
#define NOUT 256
#define NT 391
#define GRID_GEMM 148

// ---------------------------------------------------------------------------
// Device scratch
// ---------------------------------------------------------------------------
__device__ __half g_Y[(size_t)NV * HVD];              // fp16: hv@(Wl_a+Wl_b)+bl
__device__ int    g_flag[NV];
__device__ __align__(16) __half g_Bh[HVD * NOUT];     // [k][n] fp16

// SMEM layout (bytes)
#define A_STRIDE 272
#define B_STRIDE 528
#define S_A16  0                       // fp16 A tile, padded      (34816)
#define S_AF   34816                   // fp32 A stage, 128x512B   (65536)
#define S_B    100352                  // fp16 B, padded           (67584)
#define S_TOTAL 167936

__device__ __forceinline__ uint32_t smem_u32(const void* p) {
    uint32_t a;
    asm("{ .reg .u64 t; cvta.to.shared.u64 t, %1; cvt.u32.u64 %0, t; }"
        : "=r"(a) : "l"(p));
    return a;
}
#define LDMX4(r0, r1, r2, r3, a)                                              \
    asm volatile("ldmatrix.sync.aligned.m8n8.x4.shared.b16 {%0,%1,%2,%3}, [%4];" \
                 : "=r"(r0), "=r"(r1), "=r"(r2), "=r"(r3) : "r"(a))
#define LDMX4T(r0, r1, r2, r3, a)                                             \
    asm volatile("ldmatrix.sync.aligned.m8n8.x4.trans.shared.b16 {%0,%1,%2,%3}, [%4];" \
                 : "=r"(r0), "=r"(r1), "=r"(r2), "=r"(r3) : "r"(a))
#define MMA16816(d, a0, a1, a2, a3, b0, b1)                                   \
    asm volatile("mma.sync.aligned.m16n8k16.row.col.f32.f16.f16.f32 "         \
                 "{%0,%1,%2,%3}, {%4,%5,%6,%7}, {%8,%9}, {%0,%1,%2,%3};"      \
                 : "+f"((d)[0]), "+f"((d)[1]), "+f"((d)[2]), "+f"((d)[3])     \
                 : "r"(a0), "r"(a1), "r"(a2), "r"(a3), "r"(b0), "r"(b1))
#define CP_ASYNC16(dst, src)                                                  \
    asm volatile("cp.async.cg.shared.global [%0], [%1], 16;"                  \
                 :: "r"(dst), "l"(src) : "memory")
#define CP_ASYNC16Z(dst, src, vsz)                                            \
    asm volatile("cp.async.cg.shared.global [%0], [%1], 16, %2;"              \
                 :: "r"(dst), "l"(src), "r"(vsz) : "memory")
#define CP_COMMIT()   asm volatile("cp.async.commit_group;" ::: "memory")
#define CP_WAIT(n)    asm volatile("cp.async.wait_group %0;" :: "n"(n) : "memory")

// ---------------------------------------------------------------------------
// Kernel 1: zero flags + build fp16 B image.
// ---------------------------------------------------------------------------
__global__ void prep_kernel(const float* __restrict__ Wa,
                            const float* __restrict__ Wl) {
    int idx = blockIdx.x * blockDim.x + threadIdx.x;
    int stride = gridDim.x * blockDim.x;
    for (int i = idx; i < NV; i += stride) g_flag[i] = 0;
    for (int i = idx; i < HVD * NOUT; i += stride) {
        int k = i >> 8;
        int n = i & 255;
        float v;
        if (n < HVD) v = Wa[k * HVD + n];
        else {
            int c = n - HVD;
            v = Wl[k * 128 + c] + Wl[(134 + k) * 128 + c];
        }
        g_Bh[i] = __float2half_rn(v);
    }
}

// ---------------------------------------------------------------------------
// Kernel 2: mark vertices with incident edges (after clear in prep).
// ---------------------------------------------------------------------------
__global__ void flag_kernel(const int* __restrict__ eu, const int* __restrict__ ev) {
    int e = blockIdx.x * blockDim.x + threadIdx.x;
    if (e < NE) {
        g_flag[__ldg(eu + e)] = 1;
        g_flag[__ldg(ev + e)] = 1;
    }
}

// ---------------------------------------------------------------------------
// fp32 A-tile stage prefetch: 4096 16B chunks, 1024 threads x 4 iters.
// Rows >= NV zero-filled via cp.async ignore-src.
// ---------------------------------------------------------------------------
__device__ __forceinline__ void issue_a32(uint32_t dst_base,
                                          const float* __restrict__ hv,
                                          int tile, int tid) {
    const char* src = reinterpret_cast<const char*>(hv)
                    + (size_t)tile * 128 * HVD * 4;
    const int row0 = tile * 128;
    #pragma unroll
    for (int it = 0; it < 4; it++) {
        int idx = tid + it * 1024;       // 0..4095
        int row = idx >> 5;              // 32 x 16B chunks per row
        int c = idx & 31;
        int vsz = (row0 + row < NV) ? 16 : 0;
        CP_ASYNC16Z(dst_base + (uint32_t)row * 512 + (uint32_t)c * 16,
                    src + (size_t)row * 512 + (size_t)c * 16, vsz);
    }
}

// ---------------------------------------------------------------------------
// Kernel 3: persistent fp16 HMMA GEMM with in-kernel A conversion.
//   1024 threads, warp grid 4(m) x 8(n), warp tile 32x32, 256 cols at once.
//   warp_n 0..3 -> mv cols; warp_n 4..7 -> Y cols (fp16, bl folded).
// ---------------------------------------------------------------------------
__global__ void __launch_bounds__(1024, 1)
gemm_kernel(const float* __restrict__ hv,
            const float* __restrict__ ba,
            const float* __restrict__ bl,
            float* __restrict__ out_mv) {
    extern __shared__ __align__(16) unsigned char smem[];
    const uint32_t sb = smem_u32(smem);
    const int tid = threadIdx.x;
    const int wid = tid >> 5;
    const int lane = tid & 31;
    const int warp_m = wid & 3;
    const int warp_n = wid >> 2;

    // ---- B image -> SMEM once ----
    {
        const char* sh = reinterpret_cast<const char*>(g_Bh);
        #pragma unroll
        for (int it = 0; it < 4; it++) {
            int idx = tid + it * 1024;     // 0..4095
            int k = idx >> 5;
            int c = idx & 31;
            CP_ASYNC16(sb + S_B + (uint32_t)k * B_STRIDE + (uint32_t)c * 16,
                       sh + idx * 16);
        }
        CP_COMMIT();
    }

    int tile = blockIdx.x;
    issue_a32(sb + S_AF, hv, tile, tid);
    CP_COMMIT();

    const uint32_t aBase = sb + S_A16
                         + (uint32_t)(warp_m * 32 + (lane & 15)) * A_STRIDE
                         + (uint32_t)(lane >> 4) * 16;
    const uint32_t bB = sb + S_B + (uint32_t)(lane & 15) * B_STRIDE
                      + (uint32_t)(warp_n * 32 + (lane >> 4) * 8) * 2;

    while (tile < NT) {
        CP_WAIT(0);
        __syncthreads();      // stage full; all prior k-loop reads of A16 done

        // ---- convert fp32 stage -> padded fp16 A ----
        #pragma unroll
        for (int it = 0; it < 4; it++) {
            int idx = tid + it * 1024;     // 0..4095
            int row = idx >> 5;
            int c4 = idx & 31;
            float4 v = *reinterpret_cast<const float4*>(
                smem + S_AF + (size_t)row * 512 + (size_t)c4 * 16);
            __half2 h0 = __floats2half2_rn(v.x, v.y);
            __half2 h1 = __floats2half2_rn(v.z, v.w);
            uint2 pk;
            pk.x = *reinterpret_cast<uint32_t*>(&h0);
            pk.y = *reinterpret_cast<uint32_t*>(&h1);
            *reinterpret_cast<uint2*>(
                smem + S_A16 + (uint32_t)row * A_STRIDE + (uint32_t)c4 * 8) = pk;
        }
        __syncthreads();      // A16 visible; stage reads complete

        int next = tile + GRID_GEMM;
        if (next < NT) {      // overlap next-tile stage load with compute
            issue_a32(sb + S_AF, hv, next, tid);
            CP_COMMIT();
        }

        // ---- k-loop ----
        float acc[8][4];
        #pragma unroll
        for (int t = 0; t < 8; t++)
            #pragma unroll
            for (int j = 0; j < 4; j++) acc[t][j] = 0.f;

        #pragma unroll
        for (int k = 0; k < 8; k++) {
            uint32_t af[2][4], bf[2][4];
            #pragma unroll
            for (int mi = 0; mi < 2; mi++)
                LDMX4(af[mi][0], af[mi][1], af[mi][2], af[mi][3],
                      aBase + (uint32_t)k * 32 + (uint32_t)mi * (16 * A_STRIDE));
            #pragma unroll
            for (int nb = 0; nb < 2; nb++)
                LDMX4T(bf[nb][0], bf[nb][1], bf[nb][2], bf[nb][3],
                       bB + (uint32_t)k * (16 * B_STRIDE) + (uint32_t)nb * 32);
            #pragma unroll
            for (int mi = 0; mi < 2; mi++)
                #pragma unroll
                for (int ni = 0; ni < 4; ni++)
                    MMA16816(acc[mi * 4 + ni],
                             af[mi][0], af[mi][1], af[mi][2], af[mi][3],
                             bf[ni >> 1][(ni & 1) * 2], bf[ni >> 1][(ni & 1) * 2 + 1]);
        }

        // ---- epilogue ----
        const int row0 = tile * 128;
        const int r_base = row0 + warp_m * 32 + (lane >> 2);
        const int cbase = (warp_n & 3) * 32;
        if (warp_n < 4) {
            #pragma unroll
            for (int mi = 0; mi < 2; mi++) {
                int r0r = r_base + mi * 16;
                int fl0 = (r0r     < NV) ? g_flag[r0r]     : 0;
                int fl1 = (r0r + 8 < NV) ? g_flag[r0r + 8] : 0;
                #pragma unroll
                for (int ni = 0; ni < 4; ni++) {
                    int c = cbase + ni * 8 + (lane & 3) * 2;
                    float* ac = acc[mi * 4 + ni];
                    float b0 = __ldg(ba + c), b1 = __ldg(ba + c + 1);
                    #pragma unroll
                    for (int h = 0; h < 2; h++) {
                        int r = r0r + h * 8;
                        if (r >= NV) continue;
                        int fl = h ? fl1 : fl0;
                        float x0 = ac[h * 2 + 0] + b0;
                        float x1 = ac[h * 2 + 1] + b1;
                        float e0 = x0 > 0.f ? x0 : (__expf(0.01f * x0) - 1.f);
                        float e1 = x1 > 0.f ? x1 : (__expf(0.01f * x1) - 1.f);
                        e0 = fl ? e0 : 0.f;
                        e1 = fl ? e1 : 0.f;
                        asm volatile("st.global.cs.v2.f32 [%0], {%1,%2};"
                                     :: "l"(out_mv + (size_t)r * HVD + c),
                                        "f"(e0), "f"(e1) : "memory");
                    }
                }
            }
        } else {
            #pragma unroll
            for (int mi = 0; mi < 2; mi++) {
                int r0r = r_base + mi * 16;
                #pragma unroll
                for (int ni = 0; ni < 4; ni++) {
                    int cy = cbase + ni * 8 + (lane & 3) * 2;
                    float* ac = acc[mi * 4 + ni];
                    float b0 = __ldg(bl + cy), b1 = __ldg(bl + cy + 1);
                    #pragma unroll
                    for (int h = 0; h < 2; h++) {
                        int r = r0r + h * 8;
                        if (r >= NV) continue;
                        __half2 o = __floats2half2_rn(ac[h * 2 + 0] + b0,
                                                      ac[h * 2 + 1] + b1);
                        *reinterpret_cast<__half2*>(g_Y + (size_t)r * HVD + cy) = o;
                    }
                }
            }
        }
        tile = next;
    }
}

// ---------------------------------------------------------------------------
// Kernel 4: per-edge output, 4 edges per warp, fp16 Y gathers.
//   me[e] = leaky_relu(Yb[u] + Yb[v])    (at L2 throughput floor)
// ---------------------------------------------------------------------------
__global__ __launch_bounds__(256)
void edge_kernel(const int* __restrict__ eu, const int* __restrict__ ev,
                 float* __restrict__ out_me) {
    int warp = (blockIdx.x * blockDim.x + threadIdx.x) >> 5;
    int lane = threadIdx.x & 31;
    int e0 = warp * 4;
    if (e0 >= NE) return;
    const int4 us = *reinterpret_cast<const int4*>(eu + e0);
    const int4 vs = *reinterpret_cast<const int4*>(ev + e0);
    const uint2* Y = reinterpret_cast<const uint2*>(g_Y);

    uint2 a0 = __ldg(Y + (size_t)us.x * 32 + lane);
    uint2 b0 = __ldg(Y + (size_t)vs.x * 32 + lane);
    uint2 a1 = __ldg(Y + (size_t)us.y * 32 + lane);
    uint2 b1 = __ldg(Y + (size_t)vs.y * 32 + lane);
    uint2 a2 = __ldg(Y + (size_t)us.z * 32 + lane);
    uint2 b2 = __ldg(Y + (size_t)vs.z * 32 + lane);
    uint2 a3 = __ldg(Y + (size_t)us.w * 32 + lane);
    uint2 b3 = __ldg(Y + (size_t)vs.w * 32 + lane);

    float* p = out_me + (size_t)e0 * HVD + lane * 4;
#define EDGE_OUT(av, bv, idx) do {                                            \
        float2 alo = __half22float2(*reinterpret_cast<__half2*>(&av.x));      \
        float2 ahi = __half22float2(*reinterpret_cast<__half2*>(&av.y));      \
        float2 blo = __half22float2(*reinterpret_cast<__half2*>(&bv.x));      \
        float2 bhi = __half22float2(*reinterpret_cast<__half2*>(&bv.y));      \
        float4 o;                                                             \
        o.x = alo.x + blo.x; o.y = alo.y + blo.y;                             \
        o.z = ahi.x + bhi.x; o.w = ahi.y + bhi.y;                             \
        o.x = o.x > 0.f ? o.x : 0.01f * o.x;                                  \
        o.y = o.y > 0.f ? o.y : 0.01f * o.y;                                  \
        o.z = o.z > 0.f ? o.z : 0.01f * o.z;                                  \
        o.w = o.w > 0.f ? o.w : 0.01f * o.w;                                  \
        asm volatile("st.global.cs.v4.f32 [%0], {%1,%2,%3,%4};"               \
                     :: "l"(p + (idx) * HVD), "f"(o.x), "f"(o.y),             \
                        "f"(o.z), "f"(o.w) : "memory");                       \
    } while (0)
    EDGE_OUT(a0, b0, 0);
    EDGE_OUT(a1, b1, 1);
    EDGE_OUT(a2, b2, 2);
    EDGE_OUT(a3, b3, 3);
#undef EDGE_OUT
}

// ---------------------------------------------------------------------------
// Launch.  Inputs: 0 hv, 1 he, 2 p, 3 q, 4 eu, 5 ev, 6 Wa, 7 ba, 8 Wal,
//                  9 bal, 10 Wl, 11 bl.  Output: mv [50000,128] ++ me [400000,128].
// ---------------------------------------------------------------------------
extern "C" void kernel_launch(void* const* d_in, const int* in_sizes, int n_in,
                              void* d_out, int out_size) {
    const float* hv = (const float*)d_in[0];
    const int*   eu = (const int*)d_in[4];
    const int*   ev = (const int*)d_in[5];
    const float* Wa = (const float*)d_in[6];
    const float* ba = (const float*)d_in[7];
    const float* Wl = (const float*)d_in[10];
    const float* bl = (const float*)d_in[11];
    float* out = (float*)d_out;

    static bool attr_set = false;
    if (!attr_set) {
        cudaFuncSetAttribute(gemm_kernel,
                             cudaFuncAttributeMaxDynamicSharedMemorySize, S_TOTAL);
        attr_set = true;
    }

    prep_kernel<<<128, 256>>>(Wa, Wl);
    flag_kernel<<<(NE + 255) / 256, 256>>>(eu, ev);
    gemm_kernel<<<GRID_GEMM, 1024, S_TOTAL>>>(hv, ba, bl, out);
    edge_kernel<<<(NE / 4 * 32 + 255) / 256, 256>>>(eu, ev,
                                                    out + (size_t)NV * HVD);
}